// round 3
// baseline (speedup 1.0000x reference)
#include <cuda_runtime.h>
#include <cuda_bf16.h>
#include <cstdint>

#define BATCH 64
#define HDIM  1024
#define LSEQ  2048
#define NVOC  32000
#define G3    3072

// ---------------- scratch (device globals; no allocation) ----------------
__device__ __nv_bfloat16 g_xhi[BATCH*HDIM],  g_xlo[BATCH*HDIM];
__device__ __nv_bfloat16 g_hphi[2*BATCH*HDIM], g_hplo[2*BATCH*HDIM];
__device__ __nv_bfloat16 g_h0hi[BATCH*HDIM], g_h0lo[BATCH*HDIM];
__device__ float         g_gpart[8*BATCH*G3];     // [y*4+z][64][3072]
__device__ float         g_h1[BATCH*HDIM];
__device__ __nv_bfloat16 g_cathi[BATCH*2*HDIM], g_catlo[BATCH*2*HDIM];
__device__ float         g_scores[BATCH*LSEQ];
__device__ float         g_pm[BATCH*16], g_ps[BATCH*16];
__device__ float         g_pctx[BATCH*16*HDIM];
__device__ float         g_ccpart[8*BATCH*HDIM];  // [z][64][1024]
__device__ __nv_bfloat16 g_cchi[BATCH*HDIM], g_cclo[BATCH*HDIM];

// ---------------- helpers ----------------
__device__ __forceinline__ uint32_t pk_hi(float x, float y){
    return (__float_as_uint(x) >> 16) | (__float_as_uint(y) & 0xffff0000u);
}
__device__ __forceinline__ uint32_t pk_lo(float x, float y){
    float rx = x - __uint_as_float(__float_as_uint(x) & 0xffff0000u);
    float ry = y - __uint_as_float(__float_as_uint(y) & 0xffff0000u);
    return (__float_as_uint(rx) >> 16) | (__float_as_uint(ry) & 0xffff0000u);
}
__device__ __forceinline__ void split1(float v, __nv_bfloat16* hi, __nv_bfloat16* lo){
    uint32_t u  = __float_as_uint(v);
    uint32_t uh = u & 0xffff0000u;
    float r = v - __uint_as_float(uh);
    *hi = __ushort_as_bfloat16((unsigned short)(uh >> 16));
    *lo = __ushort_as_bfloat16((unsigned short)(__float_as_uint(r) >> 16));
}
__device__ __forceinline__ void mma16816(float* c, const uint32_t* a, uint32_t b0, uint32_t b1){
    asm volatile("mma.sync.aligned.m16n8k16.row.col.f32.bf16.bf16.f32 "
        "{%0,%1,%2,%3}, {%4,%5,%6,%7}, {%8,%9}, {%0,%1,%2,%3};"
        : "+f"(c[0]), "+f"(c[1]), "+f"(c[2]), "+f"(c[3])
        : "r"(a[0]), "r"(a[1]), "r"(a[2]), "r"(a[3]), "r"(b0), "r"(b1));
}

// ---------------- prep: embed gather + hi/lo split of x and h_prev ----------------
__global__ void prep_k(const int* __restrict__ seq, const float* __restrict__ embed,
                       const float* __restrict__ lh)
{
    int idx = blockIdx.x*256 + threadIdx.x;     // 3 * 65536
    int z = idx >> 16, r = idx & 65535;
    float v;
    if (z == 0){
        int b = r >> 10, j = r & 1023;
        v = embed[(size_t)seq[b]*HDIM + j];
    } else {
        v = lh[(size_t)(z-1)*BATCH*HDIM + r];
    }
    __nv_bfloat16 hi, lo; split1(v, &hi, &lo);
    if (z == 0){ g_xhi[r] = hi; g_xlo[r] = lo; }
    else       { g_hphi[(z-1)*BATCH*HDIM + r] = hi; g_hplo[(z-1)*BATCH*HDIM + r] = lo; }
}

// ---------------- generic split-precision GEMM: out = act(64xK) @ W(NxK)^T ----------------
// mode 0: layer0 GRU (y=0: x@W0, y=1: hp0@W1) -> g_gpart partials
// mode 1: layer1 GRU (y=0: h0@W0, y=1: hp1@W1) -> g_gpart partials
// mode 2: Wc: cat@Wc -> g_ccpart partials
// mode 3: Wout: cc@Wout + bias -> out_ext (direct, no split-K)
__global__ void __launch_bounds__(256, 2)
gemm_k(const float* __restrict__ W0, const float* __restrict__ W1,
       const float* __restrict__ bias, float* __restrict__ out_ext,
       int K, int N, int KS, int mode)
{
    __shared__ uint32_t smh[64*68], sml[64*68];

    int y = blockIdx.y, zz = blockIdx.z;
    const float* W = y ? W1 : W0;
    const __nv_bfloat16 *Ahp, *Alp;
    float* op;
    if (mode == 0){
        Ahp = y ? g_hphi : g_xhi;  Alp = y ? g_hplo : g_xlo;  op = g_gpart;
    } else if (mode == 1){
        Ahp = y ? (g_hphi + BATCH*HDIM) : g_h0hi;
        Alp = y ? (g_hplo + BATCH*HDIM) : g_h0lo;  op = g_gpart;
    } else if (mode == 2){
        Ahp = g_cathi; Alp = g_catlo; op = g_ccpart;
    } else {
        Ahp = g_cchi;  Alp = g_cclo;  op = out_ext;
    }
    const uint32_t* Ah = (const uint32_t*)Ahp;
    const uint32_t* Al = (const uint32_t*)Alp;

    int tid = threadIdx.x, w = tid >> 5, lane = tid & 31;
    int nblk = blockIdx.x * 128;
    int nw   = nblk + w*16;
    int r = lane >> 2, cq = (lane & 3) * 2;
    int K2 = K >> 1;

    float acc[4][2][4];
    #pragma unroll
    for (int i=0;i<4;i++)
        #pragma unroll
        for (int j=0;j<2;j++)
            #pragma unroll
            for (int q=0;q<4;q++) acc[i][j][q] = 0.f;

    int kbeg = zz * KS;
    for (int ck = kbeg; ck < kbeg + KS; ck += 128){
        __syncthreads();
        #pragma unroll
        for (int p = tid; p < 4096; p += 256){
            int m = p >> 6, kp = p & 63;
            smh[m*68 + kp] = Ah[(size_t)m*K2 + (ck>>1) + kp];
            sml[m*68 + kp] = Al[(size_t)m*K2 + (ck>>1) + kp];
        }
        __syncthreads();
        #pragma unroll
        for (int ki = 0; ki < 8; ki++){
            int kg = ck + ki*16;
            uint32_t bh[2][2], bl[2][2];
            #pragma unroll
            for (int nt = 0; nt < 2; nt++){
                const float* wp = W + (size_t)(nw + nt*8 + r)*K + kg + cq;
                float2 w0 = *(const float2*)(wp);
                float2 w1 = *(const float2*)(wp + 8);
                bh[nt][0] = pk_hi(w0.x, w0.y);  bl[nt][0] = pk_lo(w0.x, w0.y);
                bh[nt][1] = pk_hi(w1.x, w1.y);  bl[nt][1] = pk_lo(w1.x, w1.y);
            }
            int kl = (ki*16 + cq) >> 1;   // uint32 offset within smem row
            #pragma unroll
            for (int mt = 0; mt < 4; mt++){
                int rowa = mt*16 + r;
                uint32_t ah[4], al[4];
                ah[0] = smh[rowa*68 + kl];       al[0] = sml[rowa*68 + kl];
                ah[1] = smh[(rowa+8)*68 + kl];   al[1] = sml[(rowa+8)*68 + kl];
                ah[2] = smh[rowa*68 + kl + 4];   al[2] = sml[rowa*68 + kl + 4];
                ah[3] = smh[(rowa+8)*68 + kl+4]; al[3] = sml[(rowa+8)*68 + kl + 4];
                #pragma unroll
                for (int nt = 0; nt < 2; nt++){
                    mma16816(acc[mt][nt], ah, bh[nt][0], bh[nt][1]);
                    mma16816(acc[mt][nt], al, bh[nt][0], bh[nt][1]);
                    mma16816(acc[mt][nt], ah, bl[nt][0], bl[nt][1]);
                }
            }
        }
    }

    if (mode < 3){
        float* o = op + (size_t)((y*gridDim.z + zz) * 64) * N;
        #pragma unroll
        for (int mt = 0; mt < 4; mt++)
            #pragma unroll
            for (int nt = 0; nt < 2; nt++){
                int row = mt*16 + r, col = nw + nt*8 + cq;
                *(float2*)(o + (size_t)row*N + col)     = make_float2(acc[mt][nt][0], acc[mt][nt][1]);
                *(float2*)(o + (size_t)(row+8)*N + col) = make_float2(acc[mt][nt][2], acc[mt][nt][3]);
            }
    } else {
        #pragma unroll
        for (int mt = 0; mt < 4; mt++)
            #pragma unroll
            for (int nt = 0; nt < 2; nt++){
                int row = mt*16 + r, col = nw + nt*8 + cq;
                float2 bb = *(const float2*)(bias + col);
                *(float2*)(op + (size_t)row*N + col)     = make_float2(acc[mt][nt][0] + bb.x, acc[mt][nt][1] + bb.y);
                *(float2*)(op + (size_t)(row+8)*N + col) = make_float2(acc[mt][nt][2] + bb.x, acc[mt][nt][3] + bb.y);
            }
    }
}

// ---------------- GRU elementwise cell (sums split-K partials, adds biases) ----------------
__global__ void gru_cell_k(const float* __restrict__ bi, const float* __restrict__ bh,
                           const float* __restrict__ hprev, float* __restrict__ hout,
                           int layer)
{
    int idx = blockIdx.x*256 + threadIdx.x;   // 65536
    int b = idx >> 10, j = idx & 1023;
    float xr=0.f, xz=0.f, xn=0.f, hr=0.f, hz=0.f, hn=0.f;
    #pragma unroll
    for (int ks = 0; ks < 4; ks++){
        const float* gi = g_gpart + (size_t)(ks*64 + b)*G3;
        const float* gh = g_gpart + (size_t)((4+ks)*64 + b)*G3;
        xr += gi[j]; xz += gi[1024+j]; xn += gi[2048+j];
        hr += gh[j]; hz += gh[1024+j]; hn += gh[2048+j];
    }
    xr += bi[j]; xz += bi[1024+j]; xn += bi[2048+j];
    hr += bh[j]; hz += bh[1024+j]; hn += bh[2048+j];
    float rr = 1.f/(1.f + expf(-(xr+hr)));
    float zg = 1.f/(1.f + expf(-(xz+hz)));
    float nn = tanhf(xn + rr*hn);
    float h  = (1.f - zg)*nn + zg*hprev[idx];
    hout[idx] = h;
    __nv_bfloat16 hi, lo; split1(h, &hi, &lo);
    if (layer == 0){ g_h0hi[idx] = hi; g_h0lo[idx] = lo; }
    else { g_cathi[b*2048 + j] = hi; g_catlo[b*2048 + j] = lo; g_h1[idx] = h; }
}

// ---------------- attention pass 1: scores + online-softmax partial contexts ----------------
__global__ void __launch_bounds__(256, 2) attn_pass_k(const float* __restrict__ enc)
{
    __shared__ float smhv[1024];
    __shared__ float cbuf[8][1024];
    __shared__ float sm_m[8], sm_s[8];
    int b = blockIdx.x >> 4, c = blockIdx.x & 15;
    int tid = threadIdx.x, w = tid >> 5, lane = tid & 31;

    for (int i = tid; i < 1024; i += 256) smhv[i] = g_h1[b*1024 + i];
    __syncthreads();
    float hv[32];
    #pragma unroll
    for (int k = 0; k < 32; k++) hv[k] = smhv[lane + 32*k];
    float ctx[32];
    #pragma unroll
    for (int k = 0; k < 32; k++) ctx[k] = 0.f;
    float m = -1e30f, ssum = 0.f;

    for (int i = 0; i < 16; i++){
        int l = c*128 + w*16 + i;
        const float* e = enc + ((size_t)b*LSEQ + l)*1024;
        float v[32];
        #pragma unroll
        for (int k = 0; k < 32; k++) v[k] = e[lane + 32*k];
        float d = 0.f;
        #pragma unroll
        for (int k = 0; k < 32; k++) d = fmaf(v[k], hv[k], d);
        #pragma unroll
        for (int off = 16; off; off >>= 1) d += __shfl_xor_sync(0xffffffffu, d, off);
        if (lane == 0) g_scores[b*LSEQ + l] = d;
        if (d > m){
            float sc = __expf(m - d);
            ssum *= sc;
            #pragma unroll
            for (int k = 0; k < 32; k++) ctx[k] *= sc;
            m = d;
        }
        float wg = __expf(d - m);
        ssum += wg;
        #pragma unroll
        for (int k = 0; k < 32; k++) ctx[k] = fmaf(wg, v[k], ctx[k]);
    }

    if (lane == 0){ sm_m[w] = m; sm_s[w] = ssum; }
    __syncthreads();
    float mb = sm_m[0];
    #pragma unroll
    for (int jw = 1; jw < 8; jw++) mb = fmaxf(mb, sm_m[jw]);
    float sc = __expf(m - mb);
    #pragma unroll
    for (int k = 0; k < 32; k++) cbuf[w][lane + 32*k] = ctx[k] * sc;
    __syncthreads();
    for (int e2 = tid; e2 < 1024; e2 += 256){
        float s = 0.f;
        #pragma unroll
        for (int jw = 0; jw < 8; jw++) s += cbuf[jw][e2];
        g_pctx[(size_t)(b*16 + c)*1024 + e2] = s;
    }
    if (tid == 0){
        float zb = 0.f;
        #pragma unroll
        for (int jw = 0; jw < 8; jw++) zb += sm_s[jw]*__expf(sm_m[jw] - mb);
        g_pm[b*16 + c] = mb; g_ps[b*16 + c] = zb;
    }
}

// ---------------- attention finalize: weights + context ----------------
__global__ void attn_fin_k(float* __restrict__ out_attn)
{
    int b = blockIdx.x, tid = threadIdx.x;
    float M = -1e30f;
    #pragma unroll
    for (int cc = 0; cc < 16; cc++) M = fmaxf(M, g_pm[b*16 + cc]);
    float Z = 0.f;
    #pragma unroll
    for (int cc = 0; cc < 16; cc++) Z += g_ps[b*16 + cc]*__expf(g_pm[b*16 + cc] - M);
    float inv = 1.f / Z;
    for (int l = tid; l < LSEQ; l += 256)
        out_attn[b*LSEQ + l] = __expf(g_scores[b*LSEQ + l] - M) * inv;
    for (int e = tid; e < 1024; e += 256){
        float s = 0.f;
        #pragma unroll
        for (int cc = 0; cc < 16; cc++)
            s += __expf(g_pm[b*16 + cc] - M) * g_pctx[(size_t)(b*16 + cc)*1024 + e];
        float v = s * inv;
        __nv_bfloat16 hi, lo; split1(v, &hi, &lo);
        g_cathi[b*2048 + 1024 + e] = hi; g_catlo[b*2048 + 1024 + e] = lo;
    }
}

// ---------------- Wc combine: sum partials + bias + tanh + split ----------------
__global__ void cc_comb_k(const float* __restrict__ bc)
{
    int idx = blockIdx.x*256 + threadIdx.x;  // 65536
    int b = idx >> 10, n = idx & 1023;
    float s = bc[n];
    #pragma unroll
    for (int z = 0; z < 8; z++) s += g_ccpart[(size_t)(z*64 + b)*1024 + n];
    float v = tanhf(s);
    __nv_bfloat16 hi, lo; split1(v, &hi, &lo);
    g_cchi[idx] = hi; g_cclo[idx] = lo;
}

// ---------------- launch ----------------
extern "C" void kernel_launch(void* const* d_in, const int* in_sizes, int n_in,
                              void* d_out, int out_size)
{
    const int*   seq  = (const int*)d_in[0];
    const float* lh   = (const float*)d_in[1];
    const float* enc  = (const float*)d_in[2];
    const float* emb  = (const float*)d_in[3];
    const float* Wih0 = (const float*)d_in[4];
    const float* Whh0 = (const float*)d_in[5];
    const float* bih0 = (const float*)d_in[6];
    const float* bhh0 = (const float*)d_in[7];
    const float* Wih1 = (const float*)d_in[8];
    const float* Whh1 = (const float*)d_in[9];
    const float* bih1 = (const float*)d_in[10];
    const float* bhh1 = (const float*)d_in[11];
    const float* Wc   = (const float*)d_in[12];
    const float* bc   = (const float*)d_in[13];
    const float* Wout = (const float*)d_in[14];
    const float* bout = (const float*)d_in[15];

    float* out        = (float*)d_out;
    float* out_logits = out;                                   // [64, 32000]
    float* out_hidden = out + (size_t)BATCH*NVOC;              // [2, 64, 1024]
    float* out_attn   = out_hidden + 2*BATCH*HDIM;             // [64, 1, 2048]

    prep_k<<<768, 256>>>(seq, emb, lh);

    gemm_k<<<dim3(24, 2, 4), 256>>>(Wih0, Whh0, nullptr, nullptr, 1024, G3, 256, 0);
    gru_cell_k<<<256, 256>>>(bih0, bhh0, lh, out_hidden, 0);

    gemm_k<<<dim3(24, 2, 4), 256>>>(Wih1, Whh1, nullptr, nullptr, 1024, G3, 256, 1);
    gru_cell_k<<<256, 256>>>(bih1, bhh1, lh + BATCH*HDIM, out_hidden + BATCH*HDIM, 1);

    attn_pass_k<<<1024, 256>>>(enc);
    attn_fin_k<<<64, 256>>>(out_attn);

    gemm_k<<<dim3(8, 1, 8), 256>>>(Wc, nullptr, nullptr, nullptr, 2048, 1024, 256, 2);
    cc_comb_k<<<256, 256>>>(bc);

    gemm_k<<<dim3(250, 1, 1), 256>>>(Wout, nullptr, bout, out_logits, 1024, NVOC, 1024, 3);
}

// round 4
// speedup vs baseline: 1.1520x; 1.1520x over previous
#include <cuda_runtime.h>
#include <cuda_bf16.h>
#include <cstdint>

#define BATCH 64
#define HDIM  1024
#define LSEQ  2048
#define NVOC  32000
#define G3    3072

// ---------------- scratch (device globals; no allocation) ----------------
__device__ __nv_bfloat16 g_xhi[BATCH*HDIM],  g_xlo[BATCH*HDIM];
__device__ __nv_bfloat16 g_hphi[2*BATCH*HDIM], g_hplo[2*BATCH*HDIM];
__device__ __nv_bfloat16 g_h0hi[BATCH*HDIM], g_h0lo[BATCH*HDIM];
__device__ float         g_gpart[8*BATCH*G3];     // [y*4+z][64][3072]
__device__ float         g_h1[BATCH*HDIM];
__device__ __nv_bfloat16 g_cathi[BATCH*2*HDIM], g_catlo[BATCH*2*HDIM];
__device__ float         g_scores[BATCH*LSEQ];
__device__ float         g_pm[BATCH*16], g_ps[BATCH*16];
__device__ float         g_pctx[BATCH*16*HDIM];
__device__ float         g_ccpart[16*BATCH*HDIM]; // [z][64][1024]
__device__ __nv_bfloat16 g_cchi[BATCH*HDIM], g_cclo[BATCH*HDIM];

// ---------------- helpers ----------------
__device__ __forceinline__ uint32_t pk_hi(float x, float y){
    return (__float_as_uint(x) >> 16) | (__float_as_uint(y) & 0xffff0000u);
}
__device__ __forceinline__ uint32_t pk_lo(float x, float y){
    float rx = x - __uint_as_float(__float_as_uint(x) & 0xffff0000u);
    float ry = y - __uint_as_float(__float_as_uint(y) & 0xffff0000u);
    return (__float_as_uint(rx) >> 16) | (__float_as_uint(ry) & 0xffff0000u);
}
__device__ __forceinline__ void split1(float v, __nv_bfloat16* hi, __nv_bfloat16* lo){
    uint32_t u  = __float_as_uint(v);
    uint32_t uh = u & 0xffff0000u;
    float r = v - __uint_as_float(uh);
    *hi = __ushort_as_bfloat16((unsigned short)(uh >> 16));
    *lo = __ushort_as_bfloat16((unsigned short)(__float_as_uint(r) >> 16));
}
__device__ __forceinline__ void mma16816(float* c, const uint32_t* a, uint32_t b0, uint32_t b1){
    asm volatile("mma.sync.aligned.m16n8k16.row.col.f32.bf16.bf16.f32 "
        "{%0,%1,%2,%3}, {%4,%5,%6,%7}, {%8,%9}, {%0,%1,%2,%3};"
        : "+f"(c[0]), "+f"(c[1]), "+f"(c[2]), "+f"(c[3])
        : "r"(a[0]), "r"(a[1]), "r"(a[2]), "r"(a[3]), "r"(b0), "r"(b1));
}
__device__ __forceinline__ void cp16(void* sdst, const void* gsrc){
    uint32_t s = (uint32_t)__cvta_generic_to_shared(sdst);
    asm volatile("cp.async.cg.shared.global [%0], [%1], 16;" :: "r"(s), "l"(gsrc));
}

// ---------------- prep: embed gather + hi/lo split of x and h_prev ----------------
__global__ void prep_k(const int* __restrict__ seq, const float* __restrict__ embed,
                       const float* __restrict__ lh)
{
    int idx = blockIdx.x*256 + threadIdx.x;     // 3 * 65536
    int z = idx >> 16, r = idx & 65535;
    float v;
    if (z == 0){
        int b = r >> 10, j = r & 1023;
        v = embed[(size_t)seq[b]*HDIM + j];
    } else {
        v = lh[(size_t)(z-1)*BATCH*HDIM + r];
    }
    __nv_bfloat16 hi, lo; split1(v, &hi, &lo);
    if (z == 0){ g_xhi[r] = hi; g_xlo[r] = lo; }
    else       { g_hphi[(z-1)*BATCH*HDIM + r] = hi; g_hplo[(z-1)*BATCH*HDIM + r] = lo; }
}

// ---------------- split-precision GEMM v2: cp.async double-buffered ----------------
// out = act(64xK) @ W(NxK)^T  ; K-chunk = 32, W tiles fp32 in SMEM, split at frag load.
// mode 0: layer0 GRU (y=0: x@Wih, y=1: hp0@Whh) -> g_gpart
// mode 1: layer1 GRU (y=0: h0@Wih, y=1: hp1@Whh) -> g_gpart
// mode 2: Wc -> g_ccpart      mode 3: Wout + bias -> out_ext
#define GSMEM 61440
__global__ void __launch_bounds__(256, 2)
gemm2_k(const float* __restrict__ W0, const float* __restrict__ W1,
        const float* __restrict__ bias, float* __restrict__ out_ext,
        int K, int N, int KS, int mode)
{
    extern __shared__ char sraw[];
    float*    sW  = (float*)sraw;                 // [2][128][40] fp32
    uint32_t* sAh = (uint32_t*)(sraw + 40960);    // [2][64][20]
    uint32_t* sAl = (uint32_t*)(sraw + 51200);    // [2][64][20]

    int y = blockIdx.y, zz = blockIdx.z;
    const float* W = y ? W1 : W0;
    const __nv_bfloat16 *Ahp, *Alp;
    float* op;
    if (mode == 0){ Ahp = y ? g_hphi : g_xhi;  Alp = y ? g_hplo : g_xlo;  op = g_gpart; }
    else if (mode == 1){
        Ahp = y ? (g_hphi + BATCH*HDIM) : g_h0hi;
        Alp = y ? (g_hplo + BATCH*HDIM) : g_h0lo;  op = g_gpart;
    } else if (mode == 2){ Ahp = g_cathi; Alp = g_catlo; op = g_ccpart; }
    else { Ahp = g_cchi;  Alp = g_cclo;  op = out_ext; }
    const uint32_t* Agh = (const uint32_t*)Ahp;
    const uint32_t* Agl = (const uint32_t*)Alp;

    int tid = threadIdx.x, w = tid >> 5, lane = tid & 31;
    int r = lane >> 2, c = lane & 3;
    int nblk = blockIdx.x * 128;
    int K2 = K >> 1;
    int kbeg = zz * KS;
    int nch = KS >> 5;

    // chunk loader: W rows coalesced (8 threads x 16B per 128B row chunk)
    auto load_chunk = [&](int ch, int buf){
        int ck = kbeg + ch*32;
        const float* Wg = W + (size_t)nblk*K + ck;
        float* wd = sW + buf*5120;
        #pragma unroll
        for (int i = 0; i < 4; i++){
            int p = tid + i*256;
            int row = p >> 3, c4 = p & 7;
            cp16(wd + row*40 + c4*4, Wg + (size_t)row*K + c4*4);
        }
        int row = tid >> 2, c4 = tid & 3;
        const uint32_t* ah = Agh + (ck>>1) + (size_t)row*K2 + c4*4;
        const uint32_t* al = Agl + (ck>>1) + (size_t)row*K2 + c4*4;
        cp16(sAh + buf*1280 + row*20 + c4*4, ah);
        cp16(sAl + buf*1280 + row*20 + c4*4, al);
    };

    float acc[4][2][4];
    #pragma unroll
    for (int i=0;i<4;i++)
        #pragma unroll
        for (int j=0;j<2;j++)
            #pragma unroll
            for (int q=0;q<4;q++) acc[i][j][q] = 0.f;

    load_chunk(0, 0);
    asm volatile("cp.async.commit_group;");

    for (int ch = 0; ch < nch; ch++){
        int buf = ch & 1;
        if (ch + 1 < nch){
            load_chunk(ch+1, buf^1);
            asm volatile("cp.async.commit_group;");
            asm volatile("cp.async.wait_group 1;");
        } else {
            asm volatile("cp.async.wait_group 0;");
        }
        __syncthreads();

        const float2* wb = (const float2*)(sW) + buf*2560;
        const uint32_t* ab = sAh + buf*1280;
        const uint32_t* al = sAl + buf*1280;

        #pragma unroll
        for (int ki = 0; ki < 2; ki++){
            uint32_t bh[2][2], bl[2][2];
            #pragma unroll
            for (int nt = 0; nt < 2; nt++){
                int nl = w*16 + nt*8 + r;
                const float2* wp = wb + nl*20 + ki*8 + c;
                float2 w0 = wp[0], w1 = wp[4];
                bh[nt][0] = pk_hi(w0.x, w0.y);  bl[nt][0] = pk_lo(w0.x, w0.y);
                bh[nt][1] = pk_hi(w1.x, w1.y);  bl[nt][1] = pk_lo(w1.x, w1.y);
            }
            int kl = ki*8 + c;
            #pragma unroll
            for (int mt = 0; mt < 4; mt++){
                int rowa = mt*16 + r;
                uint32_t ah[4], aw[4];
                ah[0] = ab[rowa*20 + kl];        aw[0] = al[rowa*20 + kl];
                ah[1] = ab[(rowa+8)*20 + kl];    aw[1] = al[(rowa+8)*20 + kl];
                ah[2] = ab[rowa*20 + kl + 4];    aw[2] = al[rowa*20 + kl + 4];
                ah[3] = ab[(rowa+8)*20 + kl+4];  aw[3] = al[(rowa+8)*20 + kl + 4];
                #pragma unroll
                for (int nt = 0; nt < 2; nt++){
                    mma16816(acc[mt][nt], ah, bh[nt][0], bh[nt][1]);
                    mma16816(acc[mt][nt], aw, bh[nt][0], bh[nt][1]);
                    mma16816(acc[mt][nt], ah, bl[nt][0], bl[nt][1]);
                }
            }
        }
        __syncthreads();
    }

    int nw = nblk + w*16, cq = c*2;
    if (mode < 3){
        float* o = op + (size_t)((y*gridDim.z + zz) * 64) * N;
        #pragma unroll
        for (int mt = 0; mt < 4; mt++)
            #pragma unroll
            for (int nt = 0; nt < 2; nt++){
                int row = mt*16 + r, col = nw + nt*8 + cq;
                *(float2*)(o + (size_t)row*N + col)     = make_float2(acc[mt][nt][0], acc[mt][nt][1]);
                *(float2*)(o + (size_t)(row+8)*N + col) = make_float2(acc[mt][nt][2], acc[mt][nt][3]);
            }
    } else {
        #pragma unroll
        for (int mt = 0; mt < 4; mt++)
            #pragma unroll
            for (int nt = 0; nt < 2; nt++){
                int row = mt*16 + r, col = nw + nt*8 + cq;
                float2 bb = *(const float2*)(bias + col);
                *(float2*)(op + (size_t)row*N + col)     = make_float2(acc[mt][nt][0] + bb.x, acc[mt][nt][1] + bb.y);
                *(float2*)(op + (size_t)(row+8)*N + col) = make_float2(acc[mt][nt][2] + bb.x, acc[mt][nt][3] + bb.y);
            }
    }
}

// ---------------- GRU elementwise cell ----------------
__global__ void gru_cell_k(const float* __restrict__ bi, const float* __restrict__ bh,
                           const float* __restrict__ hprev, float* __restrict__ hout,
                           int layer)
{
    int idx = blockIdx.x*256 + threadIdx.x;   // 65536
    int b = idx >> 10, j = idx & 1023;
    float xr=0.f, xz=0.f, xn=0.f, hr=0.f, hz=0.f, hn=0.f;
    #pragma unroll
    for (int ks = 0; ks < 4; ks++){
        const float* gi = g_gpart + (size_t)(ks*64 + b)*G3;
        const float* gh = g_gpart + (size_t)((4+ks)*64 + b)*G3;
        xr += gi[j]; xz += gi[1024+j]; xn += gi[2048+j];
        hr += gh[j]; hz += gh[1024+j]; hn += gh[2048+j];
    }
    xr += bi[j]; xz += bi[1024+j]; xn += bi[2048+j];
    hr += bh[j]; hz += bh[1024+j]; hn += bh[2048+j];
    float rr = 1.f/(1.f + expf(-(xr+hr)));
    float zg = 1.f/(1.f + expf(-(xz+hz)));
    float nn = tanhf(xn + rr*hn);
    float h  = (1.f - zg)*nn + zg*hprev[idx];
    hout[idx] = h;
    __nv_bfloat16 hi, lo; split1(h, &hi, &lo);
    if (layer == 0){ g_h0hi[idx] = hi; g_h0lo[idx] = lo; }
    else { g_cathi[b*2048 + j] = hi; g_catlo[b*2048 + j] = lo; g_h1[idx] = h; }
}

// ---------------- attention pass 1: float4 streaming, online softmax ----------------
__global__ void __launch_bounds__(256, 2) attn_pass_k(const float* __restrict__ enc)
{
    __shared__ float4 smhv[256];
    __shared__ float cbuf[8][1024];
    __shared__ float sm_m[8], sm_s[8];
    int b = blockIdx.x >> 4, cch = blockIdx.x & 15;
    int tid = threadIdx.x, w = tid >> 5, lane = tid & 31;

    if (tid < 256) smhv[tid] = ((const float4*)g_h1)[b*256 + tid];
    __syncthreads();
    float4 hv[8];
    #pragma unroll
    for (int k = 0; k < 8; k++) hv[k] = smhv[lane + 32*k];
    float4 ctx[8];
    #pragma unroll
    for (int k = 0; k < 8; k++) ctx[k] = make_float4(0.f,0.f,0.f,0.f);
    float m = -1e30f, ssum = 0.f;

    for (int i = 0; i < 16; i++){
        int l = cch*128 + w*16 + i;
        const float4* e4 = (const float4*)(enc + ((size_t)b*LSEQ + l)*1024);
        float4 v[8];
        #pragma unroll
        for (int k = 0; k < 8; k++) v[k] = e4[lane + 32*k];
        float d = 0.f;
        #pragma unroll
        for (int k = 0; k < 8; k++){
            d = fmaf(v[k].x, hv[k].x, d); d = fmaf(v[k].y, hv[k].y, d);
            d = fmaf(v[k].z, hv[k].z, d); d = fmaf(v[k].w, hv[k].w, d);
        }
        #pragma unroll
        for (int off = 16; off; off >>= 1) d += __shfl_xor_sync(0xffffffffu, d, off);
        if (lane == 0) g_scores[b*LSEQ + l] = d;
        if (d > m){
            float sc = __expf(m - d);
            ssum *= sc;
            #pragma unroll
            for (int k = 0; k < 8; k++){
                ctx[k].x *= sc; ctx[k].y *= sc; ctx[k].z *= sc; ctx[k].w *= sc;
            }
            m = d;
        }
        float wg = __expf(d - m);
        ssum += wg;
        #pragma unroll
        for (int k = 0; k < 8; k++){
            ctx[k].x = fmaf(wg, v[k].x, ctx[k].x); ctx[k].y = fmaf(wg, v[k].y, ctx[k].y);
            ctx[k].z = fmaf(wg, v[k].z, ctx[k].z); ctx[k].w = fmaf(wg, v[k].w, ctx[k].w);
        }
    }

    if (lane == 0){ sm_m[w] = m; sm_s[w] = ssum; }
    __syncthreads();
    float mb = sm_m[0];
    #pragma unroll
    for (int jw = 1; jw < 8; jw++) mb = fmaxf(mb, sm_m[jw]);
    float sc = __expf(m - mb);
    #pragma unroll
    for (int k = 0; k < 8; k++){
        int e2 = (lane + 32*k)*4;
        cbuf[w][e2+0] = ctx[k].x*sc; cbuf[w][e2+1] = ctx[k].y*sc;
        cbuf[w][e2+2] = ctx[k].z*sc; cbuf[w][e2+3] = ctx[k].w*sc;
    }
    __syncthreads();
    for (int e2 = tid; e2 < 1024; e2 += 256){
        float s = 0.f;
        #pragma unroll
        for (int jw = 0; jw < 8; jw++) s += cbuf[jw][e2];
        g_pctx[(size_t)(b*16 + cch)*1024 + e2] = s;
    }
    if (tid == 0){
        float zb = 0.f;
        #pragma unroll
        for (int jw = 0; jw < 8; jw++) zb += sm_s[jw]*__expf(sm_m[jw] - mb);
        g_pm[b*16 + cch] = mb; g_ps[b*16 + cch] = zb;
    }
}

// ---------------- attention finalize ----------------
__global__ void attn_fin_k(float* __restrict__ out_attn)
{
    int b = blockIdx.x, tid = threadIdx.x;
    float M = -1e30f;
    #pragma unroll
    for (int cc = 0; cc < 16; cc++) M = fmaxf(M, g_pm[b*16 + cc]);
    float Z = 0.f;
    #pragma unroll
    for (int cc = 0; cc < 16; cc++) Z += g_ps[b*16 + cc]*__expf(g_pm[b*16 + cc] - M);
    float inv = 1.f / Z;
    for (int l = tid; l < LSEQ; l += 256)
        out_attn[b*LSEQ + l] = __expf(g_scores[b*LSEQ + l] - M) * inv;
    for (int e = tid; e < 1024; e += 256){
        float s = 0.f;
        #pragma unroll
        for (int cc = 0; cc < 16; cc++)
            s += __expf(g_pm[b*16 + cc] - M) * g_pctx[(size_t)(b*16 + cc)*1024 + e];
        float v = s * inv;
        __nv_bfloat16 hi, lo; split1(v, &hi, &lo);
        g_cathi[b*2048 + 1024 + e] = hi; g_catlo[b*2048 + 1024 + e] = lo;
    }
}

// ---------------- Wc combine ----------------
__global__ void cc_comb_k(const float* __restrict__ bc)
{
    int idx = blockIdx.x*256 + threadIdx.x;  // 65536
    int b = idx >> 10, n = idx & 1023;
    float s = bc[n];
    #pragma unroll
    for (int z = 0; z < 16; z++) s += g_ccpart[(size_t)(z*64 + b)*1024 + n];
    float v = tanhf(s);
    __nv_bfloat16 hi, lo; split1(v, &hi, &lo);
    g_cchi[idx] = hi; g_cclo[idx] = lo;
}

// ---------------- launch ----------------
extern "C" void kernel_launch(void* const* d_in, const int* in_sizes, int n_in,
                              void* d_out, int out_size)
{
    const int*   seq  = (const int*)d_in[0];
    const float* lh   = (const float*)d_in[1];
    const float* enc  = (const float*)d_in[2];
    const float* emb  = (const float*)d_in[3];
    const float* Wih0 = (const float*)d_in[4];
    const float* Whh0 = (const float*)d_in[5];
    const float* bih0 = (const float*)d_in[6];
    const float* bhh0 = (const float*)d_in[7];
    const float* Wih1 = (const float*)d_in[8];
    const float* Whh1 = (const float*)d_in[9];
    const float* bih1 = (const float*)d_in[10];
    const float* bhh1 = (const float*)d_in[11];
    const float* Wc   = (const float*)d_in[12];
    const float* bc   = (const float*)d_in[13];
    const float* Wout = (const float*)d_in[14];
    const float* bout = (const float*)d_in[15];

    float* out        = (float*)d_out;
    float* out_logits = out;                                   // [64, 32000]
    float* out_hidden = out + (size_t)BATCH*NVOC;              // [2, 64, 1024]
    float* out_attn   = out_hidden + 2*BATCH*HDIM;             // [64, 1, 2048]

    cudaFuncSetAttribute(gemm2_k, cudaFuncAttributeMaxDynamicSharedMemorySize, GSMEM);

    prep_k<<<768, 256>>>(seq, emb, lh);

    gemm2_k<<<dim3(24, 2, 4), 256, GSMEM>>>(Wih0, Whh0, nullptr, nullptr, 1024, G3, 256, 0);
    gru_cell_k<<<256, 256>>>(bih0, bhh0, lh, out_hidden, 0);

    gemm2_k<<<dim3(24, 2, 4), 256, GSMEM>>>(Wih1, Whh1, nullptr, nullptr, 1024, G3, 256, 1);
    gru_cell_k<<<256, 256>>>(bih1, bhh1, lh + BATCH*HDIM, out_hidden + BATCH*HDIM, 1);

    attn_pass_k<<<1024, 256>>>(enc);
    attn_fin_k<<<64, 256>>>(out_attn);

    gemm2_k<<<dim3(8, 1, 16), 256, GSMEM>>>(Wc, nullptr, nullptr, nullptr, 2048, 1024, 128, 2);
    cc_comb_k<<<256, 256>>>(bc);

    gemm2_k<<<dim3(250, 1, 1), 256, GSMEM>>>(Wout, nullptr, bout, out_logits, 1024, NVOC, 1024, 3);
}